// round 1
// baseline (speedup 1.0000x reference)
#include <cuda_runtime.h>
#include <math.h>

#define T_LEN 1024
#define KCNT  1024
#define HDIM  256
#define EDIM  64
#define TOPIC 100
#define EXLEN 768
#define GRUIN 201
#define TOPK  64

// scratch (device globals: no allocation allowed)
__device__ float g_v[TOPIC];
__device__ float g_kn[EDIM];
__device__ float g_beta_all[T_LEN];
__device__ float g_alog[KCNT];
__device__ float g_gsum[3 * HDIM];
__device__ float g_beta[TOPK];
__device__ int   g_idx[TOPK];
__device__ float g_alpha[KCNT];
__device__ float g_hkp[HDIM];

__device__ __forceinline__ float warpSum(float v) {
    #pragma unroll
    for (int o = 16; o > 0; o >>= 1) v += __shfl_down_sync(0xffffffffu, v, o);
    return v;
}

// ---------------------------------------------------------------------------
// K1a: v = W_resize @ ex_e + b_resize   (100 blocks)
//      kn = Wk @ co_e + bk              (64 blocks)
// ---------------------------------------------------------------------------
__global__ void __launch_bounds__(256) k1a(const float* __restrict__ Wr,
                                           const float* __restrict__ br,
                                           const float* __restrict__ ex,
                                           const float* __restrict__ Wk,
                                           const float* __restrict__ bk,
                                           const float* __restrict__ co) {
    int bid = blockIdx.x, tid = threadIdx.x;
    __shared__ float red[8];
    float p = 0.f;
    if (bid < TOPIC) {
        const float* row = Wr + bid * EXLEN;
        for (int i = tid; i < EXLEN; i += 256) p += row[i] * ex[i];
    } else {
        int j = bid - TOPIC;
        const float* row = Wk + j * KCNT;
        for (int i = tid; i < KCNT; i += 256) p += row[i] * co[i];
    }
    p = warpSum(p);
    if ((tid & 31) == 0) red[tid >> 5] = p;
    __syncthreads();
    if (tid < 8) {
        float s = red[tid];
        #pragma unroll
        for (int o = 4; o > 0; o >>= 1) s += __shfl_down_sync(0xffu, s, o, 8);
        if (tid == 0) {
            if (bid < TOPIC) g_v[bid] = s + br[bid];
            else             g_kn[bid - TOPIC] = s + bk[bid - TOPIC];
        }
    }
}

// ---------------------------------------------------------------------------
// K1b: beta_all = vs @ v      (blocks [0,128),  warp per row)
//      alog    = KM @ kn      (blocks [128,256))
//      gsum    = W_ih @ x     (blocks [256,352)),  x built from v,s
// ---------------------------------------------------------------------------
__global__ void __launch_bounds__(256) k1b(const float* __restrict__ vs,
                                           const float* __restrict__ KM,
                                           const float* __restrict__ Wih,
                                           const float* __restrict__ s_in) {
    int bid = blockIdx.x, tid = threadIdx.x;
    int warp = tid >> 5, lane = tid & 31;
    __shared__ float sx[GRUIN];
    if (bid < 128) {
        int t = bid * 8 + warp;
        const float* row = vs + t * TOPIC;
        float p = 0.f;
        for (int i = lane; i < TOPIC; i += 32) p += row[i] * g_v[i];
        p = warpSum(p);
        if (lane == 0) g_beta_all[t] = p;
    } else if (bid < 256) {
        int kk = (bid - 128) * 8 + warp;
        const float* row = KM + kk * EDIM;
        float p = row[lane] * g_kn[lane] + row[lane + 32] * g_kn[lane + 32];
        p = warpSum(p);
        if (lane == 0) g_alog[kk] = p;
    } else {
        float sval = s_in[0];
        float msk = (sval >= 0.5f) ? 1.f : 0.f;
        if (tid < TOPIC) {
            float vv = g_v[tid];
            sx[tid] = vv * msk;
            sx[tid + TOPIC] = vv * (1.f - msk);
        }
        if (tid == 0) sx[2 * TOPIC] = sval;
        __syncthreads();
        int j = (bid - 256) * 8 + warp;
        const float* row = Wih + j * GRUIN;
        float p = 0.f;
        for (int i = lane; i < GRUIN; i += 32) p += row[i] * sx[i];
        p = warpSum(p);
        if (lane == 0) g_gsum[j] = p;
    }
}

// ---------------------------------------------------------------------------
// K1c: bitonic top-64 + softmax -> beta/idx ; alpha softmax ; zero hkp
// ---------------------------------------------------------------------------
__global__ void __launch_bounds__(1024) k1c() {
    int tid = threadIdx.x;
    __shared__ float sv[1024];
    __shared__ int   si[1024];
    __shared__ float sred[32];
    __shared__ float sexp[64];
    __shared__ float sbc0;   // topk exp sum
    __shared__ float sbc1;   // alpha max
    __shared__ float stot;   // alpha sum

    sv[tid] = g_beta_all[tid];
    si[tid] = tid;
    __syncthreads();

    // descending bitonic sort of (val, idx)
    for (int size = 2; size <= 1024; size <<= 1) {
        for (int stride = size >> 1; stride > 0; stride >>= 1) {
            int j = tid ^ stride;
            if (j > tid) {
                float v1 = sv[tid], v2 = sv[j];
                bool up = ((tid & size) == 0);
                if (up ? (v1 < v2) : (v1 > v2)) {
                    sv[tid] = v2; sv[j] = v1;
                    int t1 = si[tid]; si[tid] = si[j]; si[j] = t1;
                }
            }
            __syncthreads();
        }
    }

    // top-64 softmax
    float mx = sv[0];
    if (tid < TOPK) sexp[tid] = expf(sv[tid] - mx);
    __syncthreads();
    if (tid == 0) {
        float s = 0.f;
        for (int i = 0; i < TOPK; i++) s += sexp[i];
        sbc0 = s;
    }
    __syncthreads();
    if (tid < TOPK) {
        g_beta[tid] = sexp[tid] / sbc0;
        g_idx[tid]  = si[tid];
    }

    // alpha = softmax(g_alog)
    float lg = g_alog[tid];
    float w = lg;
    #pragma unroll
    for (int o = 16; o > 0; o >>= 1) w = fmaxf(w, __shfl_xor_sync(0xffffffffu, w, o));
    if ((tid & 31) == 0) sred[tid >> 5] = w;
    __syncthreads();
    if (tid < 32) {
        float m2 = sred[tid];
        #pragma unroll
        for (int o = 16; o > 0; o >>= 1) m2 = fmaxf(m2, __shfl_xor_sync(0xffffffffu, m2, o));
        if (tid == 0) sbc1 = m2;
    }
    __syncthreads();
    float e = expf(lg - sbc1);
    float ws = warpSum(e);
    if ((tid & 31) == 0) sred[tid >> 5] = ws;
    __syncthreads();
    if (tid < 32) {
        float s2 = sred[tid];
        #pragma unroll
        for (int o = 16; o > 0; o >>= 1) s2 += __shfl_xor_sync(0xffffffffu, s2, o);
        if (tid == 0) stot = s2;
    }
    __syncthreads();
    g_alpha[tid] = e / stot;

    if (tid < HDIM) g_hkp[tid] = 0.f;
}

// ---------------------------------------------------------------------------
// K2: fused  (a) GRU tile GEMM + epilogue -> h_new   [bid % 5 == 0, 256 tiles]
//            (b) hs gather-reduce -> hkp atomics     [other 1024 blocks]
// Interleaved so HBM-bound gather and FMA-bound GEMM overlap on SMs.
// ---------------------------------------------------------------------------
__global__ void __launch_bounds__(256) k2(const float* __restrict__ hs,
                                          const float* __restrict__ h0,
                                          const float* __restrict__ Whh,
                                          const float* __restrict__ bih,
                                          const float* __restrict__ bhh,
                                          float* __restrict__ out) {
    __shared__ float As[16][32];
    __shared__ float Bs[3][64][33];
    int bid = blockIdx.x, tid = threadIdx.x;

    if (bid % 5 == 0) {
        // ------ GRU tile: rows k0..k0+15, cols c0..c0+63, all 3 gates ------
        int id = bid / 5;
        int rc = id & 63, ccb = id >> 6;
        int k0 = rc * 16, c0 = ccb * 64;
        int tx = tid & 63, ty = tid >> 6;
        float acc0[4] = {0, 0, 0, 0};
        float acc1[4] = {0, 0, 0, 0};
        float acc2[4] = {0, 0, 0, 0};
        int r = tid >> 5, dd = tid & 31;
        for (int d0 = 0; d0 < HDIM; d0 += 32) {
            As[r][dd]     = h0[(k0 + r) * HDIM + d0 + dd];
            As[r + 8][dd] = h0[(k0 + r + 8) * HDIM + d0 + dd];
            #pragma unroll
            for (int g = 0; g < 3; g++) {
                #pragma unroll
                for (int it = 0; it < 8; it++) {
                    int row = r + it * 8;
                    Bs[g][row][dd] = Whh[(g * HDIM + c0 + row) * HDIM + d0 + dd];
                }
            }
            __syncthreads();
            #pragma unroll 8
            for (int dd2 = 0; dd2 < 32; dd2++) {
                float b0 = Bs[0][tx][dd2];
                float b1 = Bs[1][tx][dd2];
                float b2 = Bs[2][tx][dd2];
                #pragma unroll
                for (int m = 0; m < 4; m++) {
                    float a = As[ty + 4 * m][dd2];
                    acc0[m] += a * b0;
                    acc1[m] += a * b1;
                    acc2[m] += a * b2;
                }
            }
            __syncthreads();
        }
        int c = c0 + tx;
        float gs_r = g_gsum[c],  gs_z = g_gsum[HDIM + c],  gs_n = g_gsum[2 * HDIM + c];
        float bi_r = bih[c],     bi_z = bih[HDIM + c],     bi_n = bih[2 * HDIM + c];
        float bh_r = bhh[c],     bh_z = bhh[HDIM + c],     bh_n = bhh[2 * HDIM + c];
        #pragma unroll
        for (int m = 0; m < 4; m++) {
            int k = k0 + ty + 4 * m;
            float al = g_alpha[k];
            float rg = 1.f / (1.f + expf(-(al * gs_r + bi_r + acc0[m] + bh_r)));
            float zg = 1.f / (1.f + expf(-(al * gs_z + bi_z + acc1[m] + bh_z)));
            float ng = tanhf(al * gs_n + bi_n + rg * (acc2[m] + bh_n));
            float hv = h0[k * HDIM + c];
            out[1 + k * HDIM + c] = (1.f - zg) * ng + zg * hv;
        }
    } else {
        // ------ gather: topk index i, 64-row chunk ch of hs[t] ------
        int gid = bid - (bid / 5 + 1);
        int i = gid >> 4, ch = gid & 15;
        int t = g_idx[i];
        int kb = ch * 64;
        const float* base = hs + (size_t)t * (KCNT * HDIM) + (size_t)kb * HDIM + tid;
        float acc = 0.f;
        #pragma unroll 8
        for (int r2 = 0; r2 < 64; r2++)
            acc += g_alpha[kb + r2] * base[(size_t)r2 * HDIM];
        atomicAdd(&g_hkp[tid], g_beta[i] * acc);
    }
}

// ---------------------------------------------------------------------------
// K3: predict_score = W_score @ [v ; hkp] + b_score
// ---------------------------------------------------------------------------
__global__ void __launch_bounds__(256) k3(const float* __restrict__ Wsc,
                                          const float* __restrict__ bsc,
                                          float* __restrict__ out) {
    int tid = threadIdx.x;
    __shared__ float red[8];
    float p = Wsc[TOPIC + tid] * g_hkp[tid];
    if (tid < TOPIC) p += Wsc[tid] * g_v[tid];
    p = warpSum(p);
    if ((tid & 31) == 0) red[tid >> 5] = p;
    __syncthreads();
    if (tid < 8) {
        float s = red[tid];
        #pragma unroll
        for (int o = 4; o > 0; o >>= 1) s += __shfl_down_sync(0xffu, s, o, 8);
        if (tid == 0) out[0] = s + bsc[0];
    }
}

extern "C" void kernel_launch(void* const* d_in, const int* in_sizes, int n_in,
                              void* d_out, int out_size) {
    const float* co_e = (const float*)d_in[0];
    const float* ex_e = (const float*)d_in[1];
    const float* s    = (const float*)d_in[2];
    const float* h    = (const float*)d_in[3];
    const float* vs   = (const float*)d_in[4];
    const float* hs   = (const float*)d_in[5];
    const float* Wr   = (const float*)d_in[6];
    const float* br   = (const float*)d_in[7];
    const float* Wk   = (const float*)d_in[8];
    const float* bk   = (const float*)d_in[9];
    const float* KM   = (const float*)d_in[10];
    const float* Wsc  = (const float*)d_in[11];
    const float* bsc  = (const float*)d_in[12];
    const float* Wih  = (const float*)d_in[13];
    const float* Whh  = (const float*)d_in[14];
    const float* bih  = (const float*)d_in[15];
    const float* bhh  = (const float*)d_in[16];
    float* out = (float*)d_out;

    k1a<<<TOPIC + EDIM, 256>>>(Wr, br, ex_e, Wk, bk, co_e);
    k1b<<<352, 256>>>(vs, KM, Wih, s);
    k1c<<<1, 1024>>>();
    k2<<<1280, 256>>>(hs, h, Whh, bih, bhh, out);
    k3<<<1, 256>>>(Wsc, bsc, out);
}